// round 4
// baseline (speedup 1.0000x reference)
#include <cuda_runtime.h>

#define N_MAX 100000
#define E_MAX 1000000

// ---------------- scratch (static device globals; no allocation) ----------------
__device__ float g_t[(size_t)N_MAX * 128];   // GEMM output (pre-scaled by dis[src])
__device__ float g_h[(size_t)N_MAX * 64];    // hidden activations
__device__ float g_dis[N_MAX];               // deg^{-1/2} (deg includes self-loop)
__device__ int   g_deg[N_MAX];
__device__ int   g_off[N_MAX + 1];           // CSR row offsets (by dst)
__device__ int   g_cur[N_MAX];               // scatter cursors
__device__ int   g_csr[E_MAX];               // src indices grouped by dst
__device__ int   g_bsum[256];                // scan block sums

// ---------------- CSR build ----------------
__global__ void k_zero_deg(int n) {
    int i = blockIdx.x * blockDim.x + threadIdx.x;
    if (i < n) g_deg[i] = 0;
}

__global__ void k_count(const int* __restrict__ dst, int E) {
    int e = blockIdx.x * blockDim.x + threadIdx.x;
    if (e < E) atomicAdd(&g_deg[dst[e]], 1);
}

// block-local exclusive scan over 1024 items (256 thr x 4), emit block totals
__global__ void k_scan1(int n) {
    __shared__ int sh[256];
    int t = threadIdx.x;
    int base = blockIdx.x * 1024;
    int v[4];
    int tsum = 0;
#pragma unroll
    for (int j = 0; j < 4; j++) {
        int idx = base + t * 4 + j;
        v[j] = (idx < n) ? g_deg[idx] : 0;
        tsum += v[j];
    }
    sh[t] = tsum;
    __syncthreads();
    for (int off = 1; off < 256; off <<= 1) {
        int add = (t >= off) ? sh[t - off] : 0;
        __syncthreads();
        sh[t] += add;
        __syncthreads();
    }
    int excl = (t == 0) ? 0 : sh[t - 1];
    if (t == 255) g_bsum[blockIdx.x] = sh[255];
    int run = excl;
#pragma unroll
    for (int j = 0; j < 4; j++) {
        int idx = base + t * 4 + j;
        if (idx < n) g_off[idx] = run;
        run += v[j];
    }
}

__global__ void k_scan2(int nb) {
    __shared__ int sh[256];
    int t = threadIdx.x;
    sh[t] = (t < nb) ? g_bsum[t] : 0;
    __syncthreads();
    for (int off = 1; off < 256; off <<= 1) {
        int add = (t >= off) ? sh[t - off] : 0;
        __syncthreads();
        sh[t] += add;
        __syncthreads();
    }
    int excl = (t == 0) ? 0 : sh[t - 1];
    if (t < nb) g_bsum[t] = excl;
}

__global__ void k_scan3(int n, int E) {
    int t = threadIdx.x;
    int base = blockIdx.x * 1024;
    int bo = g_bsum[blockIdx.x];
#pragma unroll
    for (int j = 0; j < 4; j++) {
        int idx = base + t * 4 + j;
        if (idx < n) {
            int o = g_off[idx] + bo;
            g_off[idx] = o;
            g_cur[idx] = o;
        }
    }
    if (blockIdx.x == 0 && t == 0) g_off[n] = E;
}

__global__ void k_fill(const int* __restrict__ src, const int* __restrict__ dst, int E) {
    int e = blockIdx.x * blockDim.x + threadIdx.x;
    if (e < E) {
        int d = dst[e];
        int pos = atomicAdd(&g_cur[d], 1);
        g_csr[pos] = src[e];
    }
}

__global__ void k_dis(int n) {
    int i = blockIdx.x * blockDim.x + threadIdx.x;
    if (i < n) g_dis[i] = rsqrtf((float)(g_deg[i] + 1));  // +1 self-loop
}

// ---------------- GEMM: y[row, col0..col0+63] = (x[row,:] @ W) * dis[row] ----------------
// K fixed at 64. W is [64, OUT] row-major. grid.y = OUT/64 selects 64-col slab.
__global__ void k_gemm64(const float* __restrict__ x, const float* __restrict__ W,
                         float* __restrict__ y, int n, int OUT) {
    __shared__ float Ws[64 * 64];
    int col0 = blockIdx.y * 64;
    for (int i = threadIdx.x; i < 64 * 64; i += blockDim.x) {
        int k = i >> 6, j = i & 63;
        Ws[i] = W[k * OUT + col0 + j];
    }
    __syncthreads();
    int row = blockIdx.x * blockDim.x + threadIdx.x;
    if (row >= n) return;

    float acc[64];
#pragma unroll
    for (int j = 0; j < 64; j++) acc[j] = 0.f;

    const float4* xr = reinterpret_cast<const float4*>(x + (size_t)row * 64);
#pragma unroll 4
    for (int k4 = 0; k4 < 16; k4++) {
        float4 xv = xr[k4];
#pragma unroll
        for (int kk = 0; kk < 4; kk++) {
            float xs = (kk == 0) ? xv.x : (kk == 1) ? xv.y : (kk == 2) ? xv.z : xv.w;
            const float4* wr = reinterpret_cast<const float4*>(&Ws[(k4 * 4 + kk) * 64]);
#pragma unroll
            for (int j4 = 0; j4 < 16; j4++) {
                float4 w = wr[j4];
                acc[j4 * 4 + 0] += xs * w.x;
                acc[j4 * 4 + 1] += xs * w.y;
                acc[j4 * 4 + 2] += xs * w.z;
                acc[j4 * 4 + 3] += xs * w.w;
            }
        }
    }
    float s = g_dis[row];
    float4* yr = reinterpret_cast<float4*>(y + (size_t)row * OUT + col0);
#pragma unroll
    for (int j4 = 0; j4 < 16; j4++) {
        yr[j4] = make_float4(acc[j4 * 4 + 0] * s, acc[j4 * 4 + 1] * s,
                             acc[j4 * 4 + 2] * s, acc[j4 * 4 + 3] * s);
    }
}

// ---------------- Aggregation: warp per node, CSR gather ----------------
// out[d] = dis[d] * (y[d] + sum_{s in N(d)} y[s]) + bias   (+ optional relu)
__global__ void k_agg64(const float* __restrict__ y, const float* __restrict__ bias,
                        float* __restrict__ out, int n, int relu) {
    int warp = (blockIdx.x * blockDim.x + threadIdx.x) >> 5;
    int lane = threadIdx.x & 31;
    if (warp >= n) return;
    int d = warp;
    const float2* yv = reinterpret_cast<const float2*>(y);
    float2 acc = yv[(size_t)d * 32 + lane];   // self-loop term
    int beg = g_off[d], end = g_off[d + 1];
    int i = beg;
    for (; i + 3 < end; i += 4) {
        int s0 = g_csr[i], s1 = g_csr[i + 1], s2 = g_csr[i + 2], s3 = g_csr[i + 3];
        float2 v0 = yv[(size_t)s0 * 32 + lane];
        float2 v1 = yv[(size_t)s1 * 32 + lane];
        float2 v2 = yv[(size_t)s2 * 32 + lane];
        float2 v3 = yv[(size_t)s3 * 32 + lane];
        acc.x += v0.x + v1.x + v2.x + v3.x;
        acc.y += v0.y + v1.y + v2.y + v3.y;
    }
    for (; i < end; i++) {
        int s = g_csr[i];
        float2 v = yv[(size_t)s * 32 + lane];
        acc.x += v.x; acc.y += v.y;
    }
    float ds = g_dis[d];
    float2 bb = reinterpret_cast<const float2*>(bias)[lane];
    float ox = acc.x * ds + bb.x;
    float oy = acc.y * ds + bb.y;
    if (relu) { ox = fmaxf(ox, 0.f); oy = fmaxf(oy, 0.f); }
    reinterpret_cast<float2*>(out)[(size_t)d * 32 + lane] = make_float2(ox, oy);
}

__global__ void k_agg128(const float* __restrict__ y, const float* __restrict__ bias,
                         float* __restrict__ out, int n) {
    int warp = (blockIdx.x * blockDim.x + threadIdx.x) >> 5;
    int lane = threadIdx.x & 31;
    if (warp >= n) return;
    int d = warp;
    const float4* yv = reinterpret_cast<const float4*>(y);
    float4 acc = yv[(size_t)d * 32 + lane];   // self-loop term
    int beg = g_off[d], end = g_off[d + 1];
    int i = beg;
    for (; i + 3 < end; i += 4) {
        int s0 = g_csr[i], s1 = g_csr[i + 1], s2 = g_csr[i + 2], s3 = g_csr[i + 3];
        float4 v0 = yv[(size_t)s0 * 32 + lane];
        float4 v1 = yv[(size_t)s1 * 32 + lane];
        float4 v2 = yv[(size_t)s2 * 32 + lane];
        float4 v3 = yv[(size_t)s3 * 32 + lane];
        acc.x += v0.x + v1.x + v2.x + v3.x;
        acc.y += v0.y + v1.y + v2.y + v3.y;
        acc.z += v0.z + v1.z + v2.z + v3.z;
        acc.w += v0.w + v1.w + v2.w + v3.w;
    }
    for (; i < end; i++) {
        int s = g_csr[i];
        float4 v = yv[(size_t)s * 32 + lane];
        acc.x += v.x; acc.y += v.y; acc.z += v.z; acc.w += v.w;
    }
    float ds = g_dis[d];
    float4 bb = reinterpret_cast<const float4*>(bias)[lane];
    float4 o = make_float4(acc.x * ds + bb.x, acc.y * ds + bb.y,
                           acc.z * ds + bb.z, acc.w * ds + bb.w);
    reinterpret_cast<float4*>(out)[(size_t)d * 32 + lane] = o;
}

// ---------------- launch ----------------
extern "C" void kernel_launch(void* const* d_in, const int* in_sizes, int n_in,
                              void* d_out, int out_size) {
    const float* x  = (const float*)d_in[0];
    const float* W1 = (const float*)d_in[1];
    const float* b1 = (const float*)d_in[2];
    const float* W2 = (const float*)d_in[3];
    const float* b2 = (const float*)d_in[4];
    const float* W3 = (const float*)d_in[5];
    const float* b3 = (const float*)d_in[6];
    const int*   ei = (const int*)d_in[7];

    int n = in_sizes[0] / 64;      // 100000
    int E = in_sizes[7] / 2;       // 1000000
    const int* src = ei;
    const int* dst = ei + E;
    float* out = (float*)d_out;

    float* t_ptr; float* h_ptr;
    cudaGetSymbolAddress((void**)&t_ptr, g_t);
    cudaGetSymbolAddress((void**)&h_ptr, g_h);

    // ---- CSR build (by dst) + normalization ----
    k_zero_deg<<<(n + 255) / 256, 256>>>(n);
    k_count<<<(E + 255) / 256, 256>>>(dst, E);
    int nb = (n + 1023) / 1024;
    k_scan1<<<nb, 256>>>(n);
    k_scan2<<<1, 256>>>(nb);
    k_scan3<<<nb, 256>>>(n, E);
    k_fill<<<(E + 255) / 256, 256>>>(src, dst, E);
    k_dis<<<(n + 255) / 256, 256>>>(n);

    int gemm_blocks = (n + 255) / 256;
    int agg_blocks  = (n * 32 + 255) / 256;

    // ---- layer 1: h = relu(agg((x@W1)*dis) * dis + b1) ----
    k_gemm64<<<dim3(gemm_blocks, 1), 256>>>(x, W1, t_ptr, n, 64);
    k_agg64<<<agg_blocks, 256>>>(t_ptr, b1, h_ptr, n, 1);

    // ---- layer 2 ----
    k_gemm64<<<dim3(gemm_blocks, 1), 256>>>(h_ptr, W2, t_ptr, n, 64);
    k_agg64<<<agg_blocks, 256>>>(t_ptr, b2, h_ptr, n, 1);

    // ---- layer 3 (OUT=128, no relu) ----
    k_gemm64<<<dim3(gemm_blocks, 2), 256>>>(h_ptr, W3, t_ptr, n, 128);
    k_agg128<<<agg_blocks, 256>>>(t_ptr, b3, out, n);
}

// round 6
// speedup vs baseline: 1.0455x; 1.0455x over previous
#include <cuda_runtime.h>

#define N_MAX 100000
#define E_MAX 1000000

// ---------------- scratch (static device globals; no allocation) ----------------
__device__ float g_t[(size_t)N_MAX * 64];    // per-layer intermediate (64-wide)
__device__ float g_h[(size_t)N_MAX * 64];    // hidden activations
__device__ float g_dis[N_MAX];               // deg^{-1/2} (deg includes self-loop)
__device__ int   g_deg[N_MAX];
__device__ int   g_off[N_MAX + 1];           // CSR row offsets (by dst)
__device__ int   g_cur[N_MAX];               // scatter cursors
__device__ int   g_csr[E_MAX];               // src indices grouped by dst
__device__ int   g_bsum[256];                // scan block sums

// ---------------- CSR build ----------------
__global__ void k_zero_deg(int n) {
    int i = blockIdx.x * blockDim.x + threadIdx.x;
    if (i < n) g_deg[i] = 0;
}

__global__ void k_count(const int* __restrict__ dst, int E) {
    int e = blockIdx.x * blockDim.x + threadIdx.x;
    if (e < E) atomicAdd(&g_deg[dst[e]], 1);
}

// block-local exclusive scan over 1024 items (256 thr x 4), emit block totals
__global__ void k_scan1(int n) {
    __shared__ int sh[256];
    int t = threadIdx.x;
    int base = blockIdx.x * 1024;
    int v[4];
    int tsum = 0;
#pragma unroll
    for (int j = 0; j < 4; j++) {
        int idx = base + t * 4 + j;
        v[j] = (idx < n) ? g_deg[idx] : 0;
        tsum += v[j];
    }
    sh[t] = tsum;
    __syncthreads();
    for (int off = 1; off < 256; off <<= 1) {
        int add = (t >= off) ? sh[t - off] : 0;
        __syncthreads();
        sh[t] += add;
        __syncthreads();
    }
    int excl = (t == 0) ? 0 : sh[t - 1];
    if (t == 255) g_bsum[blockIdx.x] = sh[255];
    int run = excl;
#pragma unroll
    for (int j = 0; j < 4; j++) {
        int idx = base + t * 4 + j;
        if (idx < n) g_off[idx] = run;
        run += v[j];
    }
}

__global__ void k_scan2(int nb) {
    __shared__ int sh[256];
    int t = threadIdx.x;
    sh[t] = (t < nb) ? g_bsum[t] : 0;
    __syncthreads();
    for (int off = 1; off < 256; off <<= 1) {
        int add = (t >= off) ? sh[t - off] : 0;
        __syncthreads();
        sh[t] += add;
        __syncthreads();
    }
    int excl = (t == 0) ? 0 : sh[t - 1];
    if (t < nb) g_bsum[t] = excl;
}

__global__ void k_scan3(int n, int E) {
    int t = threadIdx.x;
    int base = blockIdx.x * 1024;
    int bo = g_bsum[blockIdx.x];
#pragma unroll
    for (int j = 0; j < 4; j++) {
        int idx = base + t * 4 + j;
        if (idx < n) {
            int o = g_off[idx] + bo;
            g_off[idx] = o;
            g_cur[idx] = o;
        }
    }
    if (blockIdx.x == 0 && t == 0) g_off[n] = E;
}

__global__ void k_fill(const int* __restrict__ src, const int* __restrict__ dst, int E) {
    int e = blockIdx.x * blockDim.x + threadIdx.x;
    if (e < E) {
        int d = dst[e];
        int pos = atomicAdd(&g_cur[d], 1);
        g_csr[pos] = src[e];
    }
}

__global__ void k_dis(int n) {
    int i = blockIdx.x * blockDim.x + threadIdx.x;
    if (i < n) g_dis[i] = rsqrtf((float)(g_deg[i] + 1));  // +1 self-loop
}

// ---------------- GEMM (packed f32x2 FFMA2) ----------------
// K fixed at 64. W is [64, OUT] row-major. grid.y selects 64-col slab.
// mode 0: y[row, j] = (x[row,:] @ W)[j] * dis[row]          (pre-agg scaling)
// mode 1: y[row, j] = (x[row,:] @ W)[j] + bias[j]           (post-agg, final layer)
__global__ void __launch_bounds__(256) k_gemm64(const float* __restrict__ x,
                                                const float* __restrict__ W,
                                                const float* __restrict__ bias,
                                                float* __restrict__ y,
                                                int n, int OUT, int mode) {
    __shared__ __align__(16) float Ws[64 * 64];
    int col0 = blockIdx.y * 64;
    for (int i = threadIdx.x; i < 64 * 64; i += blockDim.x) {
        int k = i >> 6, j = i & 63;
        Ws[i] = W[k * OUT + col0 + j];
    }
    __syncthreads();
    int row = blockIdx.x * blockDim.x + threadIdx.x;
    if (row >= n) return;

    // 32 packed accumulators = 64 fp32 outputs
    unsigned long long acc[32];
#pragma unroll
    for (int j = 0; j < 32; j++) acc[j] = 0ULL;

    const float4* xr = reinterpret_cast<const float4*>(x + (size_t)row * 64);
#pragma unroll 4
    for (int k4 = 0; k4 < 16; k4++) {
        float4 xv = xr[k4];
#pragma unroll
        for (int kk = 0; kk < 4; kk++) {
            float xs = (kk == 0) ? xv.x : (kk == 1) ? xv.y : (kk == 2) ? xv.z : xv.w;
            unsigned int xu = __float_as_uint(xs);
            unsigned long long xp;
            asm("mov.b64 %0, {%1, %2};" : "=l"(xp) : "r"(xu), "r"(xu));
            const ulonglong2* wr =
                reinterpret_cast<const ulonglong2*>(&Ws[(k4 * 4 + kk) * 64]);
#pragma unroll
            for (int j2 = 0; j2 < 16; j2++) {
                ulonglong2 w = wr[j2];
                asm("fma.rn.f32x2 %0, %1, %2, %0;" : "+l"(acc[j2 * 2 + 0])
                    : "l"(w.x), "l"(xp));
                asm("fma.rn.f32x2 %0, %1, %2, %0;" : "+l"(acc[j2 * 2 + 1])
                    : "l"(w.y), "l"(xp));
            }
        }
    }

    float res[64];
#pragma unroll
    for (int j = 0; j < 32; j++) {
        unsigned int lo, hi;
        asm("mov.b64 {%0, %1}, %2;" : "=r"(lo), "=r"(hi) : "l"(acc[j]));
        res[j * 2 + 0] = __uint_as_float(lo);
        res[j * 2 + 1] = __uint_as_float(hi);
    }

    float4* yr = reinterpret_cast<float4*>(y + (size_t)row * OUT + col0);
    if (mode == 0) {
        float s = g_dis[row];
#pragma unroll
        for (int j4 = 0; j4 < 16; j4++)
            yr[j4] = make_float4(res[j4 * 4 + 0] * s, res[j4 * 4 + 1] * s,
                                 res[j4 * 4 + 2] * s, res[j4 * 4 + 3] * s);
    } else {
        const float4* bb4 = reinterpret_cast<const float4*>(bias + col0);
#pragma unroll
        for (int j4 = 0; j4 < 16; j4++) {
            float4 b = bb4[j4];
            yr[j4] = make_float4(res[j4 * 4 + 0] + b.x, res[j4 * 4 + 1] + b.y,
                                 res[j4 * 4 + 2] + b.z, res[j4 * 4 + 3] + b.w);
        }
    }
}

// ---------------- Aggregation: warp per node, CSR gather (64-wide) ----------------
// out[d] = dis[d] * (y[d] + sum_{s in N(d)} y[s]) [+ bias] [relu]
__global__ void __launch_bounds__(256) k_agg64(const float* __restrict__ y,
                                               const float* __restrict__ bias,
                                               float* __restrict__ out,
                                               int n, int relu) {
    int warp = (blockIdx.x * blockDim.x + threadIdx.x) >> 5;
    int lane = threadIdx.x & 31;
    if (warp >= n) return;
    int d = warp;
    const float2* yv = reinterpret_cast<const float2*>(y);
    float2 acc = yv[(size_t)d * 32 + lane];   // self-loop term
    int beg = g_off[d], end = g_off[d + 1];
    int i = beg;
    for (; i + 3 < end; i += 4) {
        int s0 = g_csr[i], s1 = g_csr[i + 1], s2 = g_csr[i + 2], s3 = g_csr[i + 3];
        float2 v0 = yv[(size_t)s0 * 32 + lane];
        float2 v1 = yv[(size_t)s1 * 32 + lane];
        float2 v2 = yv[(size_t)s2 * 32 + lane];
        float2 v3 = yv[(size_t)s3 * 32 + lane];
        acc.x += v0.x + v1.x + v2.x + v3.x;
        acc.y += v0.y + v1.y + v2.y + v3.y;
    }
    for (; i < end; i++) {
        int s = g_csr[i];
        float2 v = yv[(size_t)s * 32 + lane];
        acc.x += v.x; acc.y += v.y;
    }
    float ds = g_dis[d];
    float ox = acc.x * ds;
    float oy = acc.y * ds;
    if (bias) {
        float2 bb = reinterpret_cast<const float2*>(bias)[lane];
        ox += bb.x; oy += bb.y;
    }
    if (relu) { ox = fmaxf(ox, 0.f); oy = fmaxf(oy, 0.f); }
    reinterpret_cast<float2*>(out)[(size_t)d * 32 + lane] = make_float2(ox, oy);
}

// ---------------- launch ----------------
extern "C" void kernel_launch(void* const* d_in, const int* in_sizes, int n_in,
                              void* d_out, int out_size) {
    const float* x  = (const float*)d_in[0];
    const float* W1 = (const float*)d_in[1];
    const float* b1 = (const float*)d_in[2];
    const float* W2 = (const float*)d_in[3];
    const float* b2 = (const float*)d_in[4];
    const float* W3 = (const float*)d_in[5];
    const float* b3 = (const float*)d_in[6];
    const int*   ei = (const int*)d_in[7];

    int n = in_sizes[0] / 64;      // 100000
    int E = in_sizes[7] / 2;       // 1000000
    const int* src = ei;
    const int* dst = ei + E;
    float* out = (float*)d_out;

    float* t_ptr; float* h_ptr;
    cudaGetSymbolAddress((void**)&t_ptr, g_t);
    cudaGetSymbolAddress((void**)&h_ptr, g_h);

    // ---- CSR build (by dst) + normalization ----
    k_zero_deg<<<(n + 255) / 256, 256>>>(n);
    k_count<<<(E + 255) / 256, 256>>>(dst, E);
    int nb = (n + 1023) / 1024;
    k_scan1<<<nb, 256>>>(n);
    k_scan2<<<1, 256>>>(nb);
    k_scan3<<<nb, 256>>>(n, E);
    k_fill<<<(E + 255) / 256, 256>>>(src, dst, E);
    k_dis<<<(n + 255) / 256, 256>>>(n);

    int gemm_blocks = (n + 255) / 256;
    int agg_blocks  = (n * 32 + 255) / 256;

    // ---- layer 1: h = relu(agg((x@W1)*dis)*dis + b1) ----
    k_gemm64<<<dim3(gemm_blocks, 1), 256>>>(x, W1, nullptr, t_ptr, n, 64, 0);
    k_agg64<<<agg_blocks, 256>>>(t_ptr, b1, h_ptr, n, 1);

    // ---- layer 2 ----
    k_gemm64<<<dim3(gemm_blocks, 1), 256>>>(h_ptr, W2, nullptr, t_ptr, n, 64, 0);
    k_agg64<<<agg_blocks, 256>>>(t_ptr, b2, h_ptr, n, 1);

    // ---- layer 3 (commuted): z = dis*agg(dis*h2); out = z@W3 + b3 ----
    // scale h2 by dis first (reuse gemm mode-0 style via a tiny scale in agg):
    // agg expects y pre-scaled by dis[src]; here h2 is unscaled, so scale inside:
    // We pre-scale by writing t = h2 * dis via the agg's source values.
    // Simplest: scale h2 into t with a dedicated pass is avoidable — instead
    // reuse k_gemm64 with identity? Cheaper: fold dis into agg by scaling h2 once.
    {
        // t = h2 * dis[row]  (row-scale pass fused into agg would need dis[s]
        // per gathered row; scaling once here is 1 read + 1 write of 25MB)
        // small dedicated kernel below
        extern __global__ void k_rowscale(const float*, float*, int);
        k_rowscale<<<(n * 16 + 255) / 256, 256>>>(h_ptr, t_ptr, n);
    }
    k_agg64<<<agg_blocks, 256>>>(t_ptr, nullptr, h_ptr, n, 0);   // z in g_h
    k_gemm64<<<dim3(gemm_blocks, 2), 256>>>(h_ptr, W3, b3, out, n, 128, 1);
}

// t[row,:] = h[row,:] * dis[row]   (float4, 16 threads per row)
__global__ void __launch_bounds__(256) k_rowscale(const float* __restrict__ h,
                                                  float* __restrict__ t, int n) {
    int idx = blockIdx.x * blockDim.x + threadIdx.x;   // one float4 per thread
    int row = idx >> 4;
    if (row >= n) return;
    float s = g_dis[row];
    float4 v = reinterpret_cast<const float4*>(h)[idx];
    reinterpret_cast<float4*>(t)[idx] =
        make_float4(v.x * s, v.y * s, v.z * s, v.w * s);
}

// round 7
// speedup vs baseline: 1.5506x; 1.4831x over previous
#include <cuda_runtime.h>

#define N_MAX 100000
#define E_MAX 1000000

// ---------------- scratch (static device globals; no allocation) ----------------
__device__ float g_t[(size_t)N_MAX * 64];    // per-layer intermediate (64-wide)
__device__ float g_h[(size_t)N_MAX * 64];    // hidden activations
__device__ float g_dis[N_MAX];               // deg^{-1/2} (deg includes self-loop)
__device__ int   g_deg[N_MAX];
__device__ int   g_off[N_MAX + 1];           // CSR row offsets (by dst)
__device__ int   g_cur[N_MAX];               // scatter cursors
__device__ int   g_csr[E_MAX];               // src indices grouped by dst
__device__ int   g_bsum[256];                // scan block sums

// ---------------- CSR build ----------------
__global__ void k_zero_deg(int n) {
    int i = blockIdx.x * blockDim.x + threadIdx.x;
    if (i < n) g_deg[i] = 0;
}

__global__ void k_count(const int* __restrict__ dst, int E) {
    int e = blockIdx.x * blockDim.x + threadIdx.x;
    if (e < E) atomicAdd(&g_deg[dst[e]], 1);
}

// block-local exclusive scan over 1024 items (256 thr x 4), emit block totals
__global__ void k_scan1(int n) {
    __shared__ int sh[256];
    int t = threadIdx.x;
    int base = blockIdx.x * 1024;
    int v[4];
    int tsum = 0;
#pragma unroll
    for (int j = 0; j < 4; j++) {
        int idx = base + t * 4 + j;
        v[j] = (idx < n) ? g_deg[idx] : 0;
        tsum += v[j];
    }
    sh[t] = tsum;
    __syncthreads();
    for (int off = 1; off < 256; off <<= 1) {
        int add = (t >= off) ? sh[t - off] : 0;
        __syncthreads();
        sh[t] += add;
        __syncthreads();
    }
    int excl = (t == 0) ? 0 : sh[t - 1];
    if (t == 255) g_bsum[blockIdx.x] = sh[255];
    int run = excl;
#pragma unroll
    for (int j = 0; j < 4; j++) {
        int idx = base + t * 4 + j;
        if (idx < n) g_off[idx] = run;
        run += v[j];
    }
}

__global__ void k_scan2(int nb) {
    __shared__ int sh[256];
    int t = threadIdx.x;
    sh[t] = (t < nb) ? g_bsum[t] : 0;
    __syncthreads();
    for (int off = 1; off < 256; off <<= 1) {
        int add = (t >= off) ? sh[t - off] : 0;
        __syncthreads();
        sh[t] += add;
        __syncthreads();
    }
    int excl = (t == 0) ? 0 : sh[t - 1];
    if (t < nb) g_bsum[t] = excl;
}

// adds block offsets, writes cursors, computes dis = rsqrt(deg+1)
__global__ void k_scan3(int n, int E) {
    int t = threadIdx.x;
    int base = blockIdx.x * 1024;
    int bo = g_bsum[blockIdx.x];
#pragma unroll
    for (int j = 0; j < 4; j++) {
        int idx = base + t * 4 + j;
        if (idx < n) {
            int o = g_off[idx] + bo;
            g_off[idx] = o;
            g_cur[idx] = o;
            g_dis[idx] = rsqrtf((float)(g_deg[idx] + 1));  // +1 self-loop
        }
    }
    if (blockIdx.x == 0 && t == 0) g_off[n] = E;
}

__global__ void k_fill(const int* __restrict__ src, const int* __restrict__ dst, int E) {
    int e = blockIdx.x * blockDim.x + threadIdx.x;
    if (e < E) {
        int d = dst[e];
        int pos = atomicAdd(&g_cur[d], 1);
        g_csr[pos] = src[e];
    }
}

// ---------------- packed f32x2 helpers ----------------
__device__ __forceinline__ unsigned long long pack2(float a) {
    unsigned long long r;
    unsigned int u = __float_as_uint(a);
    asm("mov.b64 %0, {%1, %1};" : "=l"(r) : "r"(u));
    return r;
}
__device__ __forceinline__ void fma2(unsigned long long& acc, unsigned long long a,
                                     unsigned long long b) {
    asm("fma.rn.f32x2 %0, %1, %2, %0;" : "+l"(acc) : "l"(a), "l"(b));
}
__device__ __forceinline__ float2 unpack2(unsigned long long v) {
    unsigned int lo, hi;
    asm("mov.b64 {%0, %1}, %2;" : "=r"(lo), "=r"(hi) : "l"(v));
    return make_float2(__uint_as_float(lo), __uint_as_float(hi));
}

// ---------------- Tiled GEMM (128x64 block, 8x4 micro-tile, FFMA2) ----------------
// K fixed at 64. W is [64, OUT] row-major; grid.y selects 64-col slab.
// mode 0: y[row, j] = (x@W)[row,j] * dis[row]        (pre-agg scaling)
// mode 1: y[row, j] = (x@W)[row,j] + bias[j]         (final layer)
__global__ void __launch_bounds__(256) k_gemm_tiled(const float* __restrict__ x,
                                                    const float* __restrict__ W,
                                                    const float* __restrict__ bias,
                                                    float* __restrict__ y,
                                                    int n, int OUT, int mode) {
    __shared__ __align__(16) float xs[128 * 64];   // 32 KB (row-major tile)
    __shared__ __align__(16) float ws[64 * 64];    // 16 KB
    int tid = threadIdx.x;
    int row0 = blockIdx.x * 128;
    int col0 = blockIdx.y * 64;

    // load W slab: 64x64 = 1024 float4
#pragma unroll
    for (int i = 0; i < 4; i++) {
        int idx = tid + i * 256;
        int k = idx >> 4, j4 = idx & 15;
        reinterpret_cast<float4*>(ws)[idx] =
            reinterpret_cast<const float4*>(W + (size_t)k * OUT + col0)[j4];
    }
    // load x tile: 128x64 = 2048 float4 (zero-fill out-of-range rows)
#pragma unroll
    for (int i = 0; i < 8; i++) {
        int idx = tid + i * 256;
        int r = idx >> 4, j4 = idx & 15;
        float4 v = make_float4(0.f, 0.f, 0.f, 0.f);
        if (row0 + r < n)
            v = reinterpret_cast<const float4*>(x + (size_t)(row0 + r) * 64)[j4];
        reinterpret_cast<float4*>(xs)[idx] = v;
    }
    __syncthreads();

    int tx = tid & 15;        // col group: cols 4*tx .. 4*tx+3
    int ty = tid >> 4;        // row group: rows 8*ty .. 8*ty+7
    const float* xbase = xs + (ty * 8) * 64;

    unsigned long long acc[16];   // [row 0..7][colpair 0..1]
#pragma unroll
    for (int i = 0; i < 16; i++) acc[i] = 0ULL;

#pragma unroll 8
    for (int k = 0; k < 64; k++) {
        // w: 4 cols as two packed f32x2 (one LDS.128)
        ulonglong2 wv = *reinterpret_cast<const ulonglong2*>(ws + k * 64 + tx * 4);
#pragma unroll
        for (int r = 0; r < 8; r++) {
            unsigned long long xp = pack2(xbase[r * 64 + k]);
            fma2(acc[r * 2 + 0], wv.x, xp);
            fma2(acc[r * 2 + 1], wv.y, xp);
        }
    }

    // epilogue
#pragma unroll
    for (int r = 0; r < 8; r++) {
        int row = row0 + ty * 8 + r;
        if (row >= n) break;
        float2 a = unpack2(acc[r * 2 + 0]);
        float2 b = unpack2(acc[r * 2 + 1]);
        float4 o;
        if (mode == 0) {
            float s = g_dis[row];
            o = make_float4(a.x * s, a.y * s, b.x * s, b.y * s);
        } else {
            float4 bb = *reinterpret_cast<const float4*>(bias + col0 + tx * 4);
            o = make_float4(a.x + bb.x, a.y + bb.y, b.x + bb.z, b.y + bb.w);
        }
        *reinterpret_cast<float4*>(y + (size_t)row * OUT + col0 + tx * 4) = o;
    }
}

// ---------------- Aggregation: warp per node, CSR gather (64-wide) ----------------
// scale_src=0: out[d] = dis[d]*(y[d] + sum y[s]) [+bias][relu]   (y pre-scaled by dis[src])
// scale_src=1: out[d] = dis[d]*(dis[d]*y[d] + sum dis[s]*y[s])   (y unscaled)
__global__ void __launch_bounds__(256) k_agg64(const float* __restrict__ y,
                                               const float* __restrict__ bias,
                                               float* __restrict__ out,
                                               int n, int relu, int scale_src) {
    int warp = (blockIdx.x * blockDim.x + threadIdx.x) >> 5;
    int lane = threadIdx.x & 31;
    if (warp >= n) return;
    int d = warp;
    const float2* yv = reinterpret_cast<const float2*>(y);
    int beg = g_off[d], end = g_off[d + 1];
    float ds = g_dis[d];
    float2 acc;
    if (scale_src) {
        float2 self = yv[(size_t)d * 32 + lane];
        acc = make_float2(self.x * ds, self.y * ds);
        int i = beg;
        for (; i + 3 < end; i += 4) {
            int s0 = g_csr[i], s1 = g_csr[i + 1], s2 = g_csr[i + 2], s3 = g_csr[i + 3];
            float w0 = g_dis[s0], w1 = g_dis[s1], w2 = g_dis[s2], w3 = g_dis[s3];
            float2 v0 = yv[(size_t)s0 * 32 + lane];
            float2 v1 = yv[(size_t)s1 * 32 + lane];
            float2 v2 = yv[(size_t)s2 * 32 + lane];
            float2 v3 = yv[(size_t)s3 * 32 + lane];
            acc.x += v0.x * w0 + v1.x * w1 + v2.x * w2 + v3.x * w3;
            acc.y += v0.y * w0 + v1.y * w1 + v2.y * w2 + v3.y * w3;
        }
        for (; i < end; i++) {
            int s = g_csr[i];
            float w = g_dis[s];
            float2 v = yv[(size_t)s * 32 + lane];
            acc.x += v.x * w; acc.y += v.y * w;
        }
    } else {
        acc = yv[(size_t)d * 32 + lane];   // self-loop (pre-scaled)
        int i = beg;
        for (; i + 3 < end; i += 4) {
            int s0 = g_csr[i], s1 = g_csr[i + 1], s2 = g_csr[i + 2], s3 = g_csr[i + 3];
            float2 v0 = yv[(size_t)s0 * 32 + lane];
            float2 v1 = yv[(size_t)s1 * 32 + lane];
            float2 v2 = yv[(size_t)s2 * 32 + lane];
            float2 v3 = yv[(size_t)s3 * 32 + lane];
            acc.x += v0.x + v1.x + v2.x + v3.x;
            acc.y += v0.y + v1.y + v2.y + v3.y;
        }
        for (; i < end; i++) {
            int s = g_csr[i];
            float2 v = yv[(size_t)s * 32 + lane];
            acc.x += v.x; acc.y += v.y;
        }
    }
    float ox = acc.x * ds;
    float oy = acc.y * ds;
    if (bias) {
        float2 bb = reinterpret_cast<const float2*>(bias)[lane];
        ox += bb.x; oy += bb.y;
    }
    if (relu) { ox = fmaxf(ox, 0.f); oy = fmaxf(oy, 0.f); }
    reinterpret_cast<float2*>(out)[(size_t)d * 32 + lane] = make_float2(ox, oy);
}

// ---------------- launch ----------------
extern "C" void kernel_launch(void* const* d_in, const int* in_sizes, int n_in,
                              void* d_out, int out_size) {
    const float* x  = (const float*)d_in[0];
    const float* W1 = (const float*)d_in[1];
    const float* b1 = (const float*)d_in[2];
    const float* W2 = (const float*)d_in[3];
    const float* b2 = (const float*)d_in[4];
    const float* W3 = (const float*)d_in[5];
    const float* b3 = (const float*)d_in[6];
    const int*   ei = (const int*)d_in[7];

    int n = in_sizes[0] / 64;      // 100000
    int E = in_sizes[7] / 2;       // 1000000
    const int* src = ei;
    const int* dst = ei + E;
    float* out = (float*)d_out;

    float* t_ptr; float* h_ptr;
    cudaGetSymbolAddress((void**)&t_ptr, g_t);
    cudaGetSymbolAddress((void**)&h_ptr, g_h);

    // ---- CSR build (by dst) + normalization ----
    k_zero_deg<<<(n + 255) / 256, 256>>>(n);
    k_count<<<(E + 255) / 256, 256>>>(dst, E);
    int nb = (n + 1023) / 1024;
    k_scan1<<<nb, 256>>>(n);
    k_scan2<<<1, 256>>>(nb);
    k_scan3<<<nb, 256>>>(n, E);
    k_fill<<<(E + 255) / 256, 256>>>(src, dst, E);

    int gemm_blocks = (n + 127) / 128;
    int agg_blocks  = (n * 32 + 255) / 256;

    // ---- layer 1: h = relu(agg((x@W1)*dis)*dis + b1) ----
    k_gemm_tiled<<<dim3(gemm_blocks, 1), 256>>>(x, W1, nullptr, t_ptr, n, 64, 0);
    k_agg64<<<agg_blocks, 256>>>(t_ptr, b1, h_ptr, n, 1, 0);

    // ---- layer 2 ----
    k_gemm_tiled<<<dim3(gemm_blocks, 1), 256>>>(h_ptr, W2, nullptr, t_ptr, n, 64, 0);
    k_agg64<<<agg_blocks, 256>>>(t_ptr, b2, h_ptr, n, 1, 0);

    // ---- layer 3 (commuted): z = dis*agg(dis*h2)  (scale fused into agg);
    //      out = z@W3 + b3 ----
    k_agg64<<<agg_blocks, 256>>>(h_ptr, nullptr, t_ptr, n, 0, 1);
    k_gemm_tiled<<<dim3(gemm_blocks, 2), 256>>>(t_ptr, W3, b3, out, n, 128, 1);
}